// round 4
// baseline (speedup 1.0000x reference)
#include <cuda_runtime.h>
#include <math.h>

#define Bn 8
#define Hn 192
#define Wn 192
#define NTOT (Bn*Hn*Wn)

// Scratch (device globals -- no dynamic allocation allowed).
// s8[tensor][mask(0=fg,1=bg)][b][h][w] = column-pass nearest-zero distance
// (255 sentinel = no zero in column -> behaves like reference's INF=1e12)
__device__ unsigned char g_s8[2][2][Bn][Hn][Wn];
__device__ int   g_hasfg[2][Bn];
__device__ float g_part[Bn*Hn];

// ---------------------------------------------------------------------------
// Kernel A: masks + 1D column distance transform (along H), both fg and bg
// masks in a single pair of sweeps. One block per (tensor,b), thread = column.
// Also computes has_fg per (tensor, batch) via block-wide OR (deterministic,
// single owning block -> plain store, no pre-zeroing kernel needed).
// ---------------------------------------------------------------------------
__global__ void colpass_kernel(const float* __restrict__ pred,
                               const float* __restrict__ tgt) {
    const int t = blockIdx.x >> 3;      // 0 = pred, 1 = target
    const int b = blockIdx.x & 7;
    const float* src = (t == 0) ? pred : tgt;
    const int w = threadIdx.x;

    int dF = 255, dB = 255;             // dist to nearest bg / nearest fg
    int anyfg = 0;

    // top -> bottom sweep
    #pragma unroll 4
    for (int h = 0; h < Hn; ++h) {
        float v = src[(b * Hn + h) * Wn + w];
        // pred mask: sigmoid(v) > 0.5  <=>  v > 0
        bool fg = (t == 0) ? (v > 0.0f) : (v > 0.5f);
        anyfg |= (int)fg;
        dF = fg ? min(dF + 1, 255) : 0;
        dB = fg ? 0 : min(dB + 1, 255);
        g_s8[t][0][b][h][w] = (unsigned char)dF;
        g_s8[t][1][b][h][w] = (unsigned char)dB;
    }

    // bottom -> top sweep, combine with stored forward distances
    dF = 255; dB = 255;
    #pragma unroll 4
    for (int h = Hn - 1; h >= 0; --h) {
        int sF = (int)g_s8[t][0][b][h][w];
        int sB = (int)g_s8[t][1][b][h][w];
        bool fg = (sF > 0);             // forward pass stored 0 iff bg pixel
        dF = fg ? min(dF + 1, 255) : 0;
        dB = fg ? 0 : min(dB + 1, 255);
        if (dF < sF) g_s8[t][0][b][h][w] = (unsigned char)dF;
        if (dB < sB) g_s8[t][1][b][h][w] = (unsigned char)dB;
    }

    int r = __syncthreads_or(anyfg);
    if (threadIdx.x == 0) g_hasfg[t][b] = r ? 1 : 0;
}

// ---------------------------------------------------------------------------
// Kernel B: 1D row DT (along W) with early-terminating window search,
// fused with the loss elementwise math and a deterministic block reduction.
// One block per (b, h), thread = output column p.
//
// D[p] = min_q (p-q)^2 + s_q^2.  best starts at s_p^2; all terms at offset d
// are >= d^2, so stopping at d^2 >= best yields the exact minimum. For random
// ~50% masks the expected window is 1-3 iterations.
// ---------------------------------------------------------------------------
__global__ void rowpass_kernel(const float* __restrict__ pred,
                               const float* __restrict__ tgt) {
    const int b = blockIdx.x / Hn;
    const int h = blockIdx.x % Hn;
    const int p = threadIdx.x;

    __shared__ float ssq[4][Wn];        // squared column distances, 4 masks
    __shared__ float wsum[6];

    #pragma unroll
    for (int k = 0; k < 4; ++k) {
        unsigned char c = g_s8[k >> 1][k & 1][b][h][p];
        float s = (c == 255) ? 1.0e6f : (float)c;   // 1e6^2 = 1e12 = ref INF
        ssq[k][p] = s * s;
    }
    __syncthreads();

    float D[4];
    #pragma unroll
    for (int m = 0; m < 4; ++m) {
        float best = ssq[m][p];
        for (int d = 1; d < Wn; ++d) {
            float dd = (float)(d * d);
            if (dd >= best) break;
            int lo = p - d, hi = p + d;
            if (lo >= 0)  best = fminf(best, dd + ssq[m][lo]);
            if (hi < Wn)  best = fminf(best, dd + ssq[m][hi]);
        }
        D[m] = best;
    }

    const float ffp = (float)g_hasfg[0][b];
    const float fft = (float)g_hasfg[1][b];

    float pd = (sqrtf(D[0]) + sqrtf(D[1])) * ffp;   // pred distance field
    float td = (sqrtf(D[2]) + sqrtf(D[3])) * fft;   // target distance field

    const int idx = (b * Hn + h) * Wn + p;
    float x  = pred[idx];
    float tv = tgt[idx];
    float sg = 1.0f / (1.0f + expf(-x));
    float e  = sg - tv;
    e = e * e;

    float num = pd * pd + td * td;
    float den = pd + td;
    den = den * den;
    float contrib = e * (num / den);

    // deterministic block reduction: warp shuffles + fixed-order smem combine
    float v = contrib;
    #pragma unroll
    for (int o = 16; o > 0; o >>= 1)
        v += __shfl_down_sync(0xffffffffu, v, o);
    if ((p & 31) == 0) wsum[p >> 5] = v;
    __syncthreads();
    if (p == 0) {
        float s = 0.0f;
        #pragma unroll
        for (int i = 0; i < 6; ++i) s += wsum[i];
        g_part[blockIdx.x] = s;
    }
}

// ---------------------------------------------------------------------------
// Kernel C: deterministic final reduction of the 1536 per-block partials
// in fp64, write scalar mean.
// ---------------------------------------------------------------------------
__global__ void finish_kernel(float* __restrict__ out) {
    __shared__ double sm[256];
    const int tid = threadIdx.x;
    double s = 0.0;
    for (int i = tid; i < Bn * Hn; i += 256)
        s += (double)g_part[i];
    sm[tid] = s;
    __syncthreads();
    #pragma unroll
    for (int o = 128; o > 0; o >>= 1) {
        if (tid < o) sm[tid] += sm[tid + o];
        __syncthreads();
    }
    if (tid == 0) out[0] = (float)(sm[0] / (double)NTOT);
}

extern "C" void kernel_launch(void* const* d_in, const int* in_sizes, int n_in,
                              void* d_out, int out_size) {
    const float* pred = (const float*)d_in[0];
    const float* tgt  = (const float*)d_in[1];
    float* out = (float*)d_out;
    (void)in_sizes; (void)n_in; (void)out_size;

    colpass_kernel<<<16, Wn>>>(pred, tgt);
    rowpass_kernel<<<Bn * Hn, Wn>>>(pred, tgt);
    finish_kernel<<<1, 256>>>(out);
}

// round 7
// speedup vs baseline: 2.1892x; 2.1892x over previous
#include <cuda_runtime.h>
#include <math.h>

#define Bn 8
#define Hn 192
#define Wn 192
#define NTOT (Bn*Hn*Wn)
#define NCH 6                     // 192 rows = 6 x 32-bit words

// fg bitmask per column: g_mask[tensor][b][chunk][w], bit i of chunk j = row 32j+i
__device__ unsigned g_mask[2][Bn][NCH][Wn];
__device__ int      g_hasany[2][Bn][NCH];
__device__ float    g_part[Bn*Hn];

// ---------------------------------------------------------------------------
// Kernel A: build per-column fg bitmasks. One block per (tensor, b, row-chunk).
// 32 independent loads per thread -> full MLP, one streaming pass over inputs.
// ---------------------------------------------------------------------------
__global__ void mask_kernel(const float* __restrict__ pred,
                            const float* __restrict__ tgt) {
    const int blk = blockIdx.x;               // t*48 + b*6 + chunk
    const int t = blk / (Bn * NCH);
    const int r = blk % (Bn * NCH);
    const int b = r / NCH;
    const int chunk = r % NCH;
    const float* src = t ? tgt : pred;
    const int w = threadIdx.x;
    const int h0 = chunk * 32;

    unsigned mword = 0;
    #pragma unroll
    for (int i = 0; i < 32; ++i) {
        float v = src[(b * Hn + h0 + i) * Wn + w];
        // pred mask: sigmoid(v) > 0.5 <=> v > 0
        bool fg = t ? (v > 0.5f) : (v > 0.0f);
        mword |= (unsigned)fg << i;
    }
    g_mask[t][b][chunk][w] = mword;

    int any = __syncthreads_or(mword != 0u);
    if (w == 0) g_hasany[t][b][chunk] = any;
}

// distance from row h to nearest set bit in 192-bit mask m[6]; BIG if none
#define BIGD (1 << 20)
__device__ __forceinline__ int nearest_set(const unsigned m[NCH], int h) {
    const int c = h >> 5, bit = h & 31;
    int down = BIGD, up = BIGD;

    unsigned x = m[c] & (0xFFFFFFFFu << bit);          // bits >= h in word c
    if (x) down = (__ffs(x) - 1) - bit;
    else {
        #pragma unroll
        for (int j = 1; j < NCH; ++j) {
            int jj = c + j;
            if (jj < NCH && m[jj]) { down = (jj * 32 + __ffs(m[jj]) - 1) - h; break; }
        }
    }
    x = m[c] & (0xFFFFFFFFu >> (31 - bit));            // bits <= h in word c
    if (x) up = bit - (31 - __clz(x));
    else {
        #pragma unroll
        for (int j = 1; j < NCH; ++j) {
            int jj = c - j;
            if (jj >= 0 && m[jj]) { up = h - (jj * 32 + 31 - __clz(m[jj])); break; }
        }
    }
    return min(up, down);
}

// ---------------------------------------------------------------------------
// Kernel B: column distances from bitmasks (O(6) bit ops, no scan) + windowed
// exact 1D row DT + fused loss elementwise math + deterministic reduction.
// One block per (b, h), thread = output column p.
// ---------------------------------------------------------------------------
__global__ void rowpass_kernel(const float* __restrict__ pred,
                               const float* __restrict__ tgt) {
    const int b = blockIdx.x / Hn;
    const int h = blockIdx.x % Hn;
    const int p = threadIdx.x;

    __shared__ float ssq[4][Wn];       // squared col distances, 4 masks
    __shared__ float wsum[6];

    unsigned mp[NCH], mpc[NCH], mt[NCH], mtc[NCH];
    #pragma unroll
    for (int j = 0; j < NCH; ++j) {
        mp[j] = g_mask[0][b][j][p];  mpc[j] = ~mp[j];
        mt[j] = g_mask[1][b][j][p];  mtc[j] = ~mt[j];
    }
    // fg EDT column dist = nearest bg (zero bit); bg EDT = nearest fg (set bit)
    int s0 = nearest_set(mpc, h);      // pred fg EDT
    int s1 = nearest_set(mp,  h);      // pred bg EDT
    int s2 = nearest_set(mtc, h);      // tgt  fg EDT
    int s3 = nearest_set(mt,  h);      // tgt  bg EDT
    ssq[0][p] = (s0 >= BIGD) ? 1.0e12f : (float)(s0 * s0);
    ssq[1][p] = (s1 >= BIGD) ? 1.0e12f : (float)(s1 * s1);
    ssq[2][p] = (s2 >= BIGD) ? 1.0e12f : (float)(s2 * s2);
    ssq[3][p] = (s3 >= BIGD) ? 1.0e12f : (float)(s3 * s3);
    __syncthreads();

    // exact min_q (p-q)^2 + s_q^2 with outward early-terminating window:
    // all candidates at offset d contribute >= d^2, so stop when d^2 >= best.
    float D[4];
    #pragma unroll
    for (int m = 0; m < 4; ++m) {
        float best = ssq[m][p];
        for (int d = 1; d < Wn; ++d) {
            float dd = (float)(d * d);
            if (dd >= best) break;
            int lo = p - d, hi = p + d;
            if (lo >= 0)  best = fminf(best, dd + ssq[m][lo]);
            if (hi < Wn)  best = fminf(best, dd + ssq[m][hi]);
        }
        D[m] = best;
    }

    int hp = 0, ht = 0;
    #pragma unroll
    for (int j = 0; j < NCH; ++j) {
        hp |= g_hasany[0][b][j];
        ht |= g_hasany[1][b][j];
    }

    float pd = (sqrtf(D[0]) + sqrtf(D[1])) * (float)hp;  // pred distance field
    float td = (sqrtf(D[2]) + sqrtf(D[3])) * (float)ht;  // target distance field

    const int idx = (b * Hn + h) * Wn + p;
    float x  = pred[idx];
    float tv = tgt[idx];
    float sg = 1.0f / (1.0f + expf(-x));
    float e  = sg - tv;
    e = e * e;

    float num = pd * pd + td * td;
    float den = pd + td;
    den = den * den;
    float contrib = e * (num / den);

    // deterministic block reduction
    float v = contrib;
    #pragma unroll
    for (int o = 16; o > 0; o >>= 1)
        v += __shfl_down_sync(0xffffffffu, v, o);
    if ((p & 31) == 0) wsum[p >> 5] = v;
    __syncthreads();
    if (p == 0) {
        float s = 0.0f;
        #pragma unroll
        for (int i = 0; i < 6; ++i) s += wsum[i];
        g_part[blockIdx.x] = s;
    }
}

// ---------------------------------------------------------------------------
// Kernel C: deterministic final reduction (fp64) -> scalar mean.
// ---------------------------------------------------------------------------
__global__ void finish_kernel(float* __restrict__ out) {
    __shared__ double sm[256];
    const int tid = threadIdx.x;
    double s = 0.0;
    for (int i = tid; i < Bn * Hn; i += 256)
        s += (double)g_part[i];
    sm[tid] = s;
    __syncthreads();
    #pragma unroll
    for (int o = 128; o > 0; o >>= 1) {
        if (tid < o) sm[tid] += sm[tid + o];
        __syncthreads();
    }
    if (tid == 0) out[0] = (float)(sm[0] / (double)NTOT);
}

extern "C" void kernel_launch(void* const* d_in, const int* in_sizes, int n_in,
                              void* d_out, int out_size) {
    const float* pred = (const float*)d_in[0];
    const float* tgt  = (const float*)d_in[1];
    float* out = (float*)d_out;
    (void)in_sizes; (void)n_in; (void)out_size;

    mask_kernel<<<2 * Bn * NCH, Wn>>>(pred, tgt);
    rowpass_kernel<<<Bn * Hn, Wn>>>(pred, tgt);
    finish_kernel<<<1, 256>>>(out);
}